// round 7
// baseline (speedup 1.0000x reference)
#include <cuda_runtime.h>
#include <math.h>
#include <stdint.h>

#define BATCH 8
#define SEQ   256
#define F0    512
#define F1    256
#define F2    128
#define KMAX  30
#define CLUS  8       // CTAs per cluster = blocks per batch
#define DPT   512     // threads per dp block (16 warps, 2 rows/warp)

// ---- scratch (__device__ globals; no allocations allowed) ----
__device__ float g_h[BATCH*SEQ*F1];
__device__ float g_z[BATCH*SEQ*F2];
__device__ float g_corr[BATCH*SEQ*SEQ];
__device__ float g_P[BATCH*SEQ*SEQ];
__device__ float g_diag[BATCH][SEQ];

// ---- dynamic smem layout for dp_kernel ----
#define SC_OFF    0                      // sC[KMAX][SEQ+2]        30960 B
#define T_OFF     30960                  // T[32][SEQ] / s_acc[16][SEQ] overlay  32768 B
#define SEG_OFF   63728                  // segTot[8][SEQ]          8192 B
#define OFFV_OFF  71920                  // offv[SEQ]               1024 B
#define PART_OFF  72944                  // partbuf[8][SEQ]         8192 B
#define DSM_BYTES 81136

// ---- packed fp32x2 helpers (FFMA2) ----
__device__ __forceinline__ void ffma2(unsigned long long& d,
                                      unsigned long long a,
                                      unsigned long long b) {
    asm("fma.rn.f32x2 %0, %1, %2, %0;" : "+l"(d) : "l"(a), "l"(b));
}
__device__ __forceinline__ void unpack2(unsigned long long v, float& lo, float& hi) {
    asm("mov.b64 {%0,%1}, %2;" : "=f"(lo), "=f"(hi) : "l"(v));
}

// ---- cluster / DSMEM helpers ----
__device__ __forceinline__ uint32_t smem_u32(const void* p) {
    return (uint32_t)__cvta_generic_to_shared(p);
}
__device__ __forceinline__ void dsmem_st(uint32_t addr, int rank, float v) {
    uint32_t r;
    asm volatile("mapa.shared::cluster.u32 %0, %1, %2;" : "=r"(r) : "r"(addr), "r"(rank));
    asm volatile("st.shared::cluster.f32 [%0], %1;" :: "r"(r), "f"(v));
}
__device__ __forceinline__ void cluster_sync_() {
    asm volatile("barrier.cluster.arrive.aligned;" ::: "memory");
    asm volatile("barrier.cluster.wait.aligned;" ::: "memory");
}

// ============================================================
// GEMM: C[M,N] = (A[M,K] @ B[K,N]) + bias, optional relu. FFMA2.
// ============================================================
template<int RELU>
__global__ __launch_bounds__(256) void gemm_kernel(
    const float* __restrict__ A, const float* __restrict__ B,
    const float* __restrict__ bias, float* __restrict__ C,
    int M, int N, int K)
{
    __shared__ float As2[16][128];
    __shared__ float Bs[16][64];
    const int m0 = blockIdx.y * 64, n0 = blockIdx.x * 64;
    const int tid = threadIdx.x;
    const int ty = tid >> 4, tx = tid & 15;
    const int arow = tid >> 2, akq = tid & 3;
    const int bkr  = tid >> 4, bnq = tid & 15;

    unsigned long long acc2[4][2] = {};

    for (int k0 = 0; k0 < K; k0 += 16) {
        float4 va = *(const float4*)(A + (size_t)(m0 + arow) * K + k0 + akq * 4);
        *(float2*)&As2[akq*4+0][2*arow] = make_float2(va.x, va.x);
        *(float2*)&As2[akq*4+1][2*arow] = make_float2(va.y, va.y);
        *(float2*)&As2[akq*4+2][2*arow] = make_float2(va.z, va.z);
        *(float2*)&As2[akq*4+3][2*arow] = make_float2(va.w, va.w);
        float4 vb = *(const float4*)(B + (size_t)(k0 + bkr) * N + n0 + bnq * 4);
        *(float4*)&Bs[bkr][bnq*4] = vb;
        __syncthreads();
        #pragma unroll
        for (int k = 0; k < 16; k++) {
            ulonglong2 a01 = *(const ulonglong2*)&As2[k][ty*8];
            ulonglong2 a23 = *(const ulonglong2*)&As2[k][ty*8 + 4];
            ulonglong2 bq  = *(const ulonglong2*)&Bs[k][tx*4];
            ffma2(acc2[0][0], a01.x, bq.x); ffma2(acc2[0][1], a01.x, bq.y);
            ffma2(acc2[1][0], a01.y, bq.x); ffma2(acc2[1][1], a01.y, bq.y);
            ffma2(acc2[2][0], a23.x, bq.x); ffma2(acc2[2][1], a23.x, bq.y);
            ffma2(acc2[3][0], a23.y, bq.x); ffma2(acc2[3][1], a23.y, bq.y);
        }
        __syncthreads();
    }

    #pragma unroll
    for (int r = 0; r < 4; r++) {
        int m = m0 + ty*4 + r;
        #pragma unroll
        for (int c2 = 0; c2 < 2; c2++) {
            float v0, v1;
            unpack2(acc2[r][c2], v0, v1);
            int n = n0 + tx*4 + c2*2;
            v0 += bias[n]; v1 += bias[n+1];
            if (RELU) { v0 = fmaxf(v0, 0.0f); v1 = fmaxf(v1, 0.0f); }
            *(float2*)(C + (size_t)m * N + n) = make_float2(v0, v1);
        }
    }
}

// ============================================================
// corr[b] = z_b @ z_b^T (NT, M=N=256, K=128) via FFMA2 + diag capture.
// ============================================================
__global__ __launch_bounds__(256) void syrk_kernel()
{
    __shared__ float As2[16][128];
    __shared__ float Bs[16][64];
    const int bz = blockIdx.z;
    const float* Z = g_z + (size_t)bz * SEQ * F2;
    float* C = g_corr + (size_t)bz * SEQ * SEQ;
    const int m0 = blockIdx.y * 64, n0 = blockIdx.x * 64;
    const int tid = threadIdx.x;
    const int ty = tid >> 4, tx = tid & 15;
    const int row = tid >> 2, kq = tid & 3;

    unsigned long long acc2[4][2] = {};

    for (int k0 = 0; k0 < F2; k0 += 16) {
        float4 va = *(const float4*)(Z + (size_t)(m0 + row) * F2 + k0 + kq * 4);
        *(float2*)&As2[kq*4+0][2*row] = make_float2(va.x, va.x);
        *(float2*)&As2[kq*4+1][2*row] = make_float2(va.y, va.y);
        *(float2*)&As2[kq*4+2][2*row] = make_float2(va.z, va.z);
        *(float2*)&As2[kq*4+3][2*row] = make_float2(va.w, va.w);
        float4 vb = *(const float4*)(Z + (size_t)(n0 + row) * F2 + k0 + kq * 4);
        Bs[kq*4+0][row] = vb.x; Bs[kq*4+1][row] = vb.y;
        Bs[kq*4+2][row] = vb.z; Bs[kq*4+3][row] = vb.w;
        __syncthreads();
        #pragma unroll
        for (int k = 0; k < 16; k++) {
            ulonglong2 a01 = *(const ulonglong2*)&As2[k][ty*8];
            ulonglong2 a23 = *(const ulonglong2*)&As2[k][ty*8 + 4];
            ulonglong2 bq  = *(const ulonglong2*)&Bs[k][tx*4];
            ffma2(acc2[0][0], a01.x, bq.x); ffma2(acc2[0][1], a01.x, bq.y);
            ffma2(acc2[1][0], a01.y, bq.x); ffma2(acc2[1][1], a01.y, bq.y);
            ffma2(acc2[2][0], a23.x, bq.x); ffma2(acc2[2][1], a23.x, bq.y);
            ffma2(acc2[3][0], a23.y, bq.x); ffma2(acc2[3][1], a23.y, bq.y);
        }
        __syncthreads();
    }

    #pragma unroll
    for (int r = 0; r < 4; r++) {
        int m = m0 + ty*4 + r;
        #pragma unroll
        for (int c2 = 0; c2 < 2; c2++) {
            float v0, v1;
            unpack2(acc2[r][c2], v0, v1);
            int n = n0 + tx*4 + c2*2;
            C[(size_t)m * SEQ + n]     = v0;
            C[(size_t)m * SEQ + n + 1] = v1;
            if (m == n)     g_diag[bz][m] = v0;
            if (m == n + 1) g_diag[bz][m] = v1;
        }
    }
}

// ============================================================
// dp_kernel: scan(D->P) + 29-step min-DP + softmax + output,
// all in one launch. Grid 64 blocks, cluster of 8 = one batch.
// Cross-CTA exchange via DSMEM + barrier.cluster (no atomics,
// no gmem roundtrip on the DP critical path).
// ============================================================
__global__ __launch_bounds__(DPT) __cluster_dims__(CLUS, 1, 1)
void dp_kernel(float* __restrict__ out)
{
    extern __shared__ char dsm[];
    float (*sC)[SEQ+2]    = (float(*)[SEQ+2])(dsm + SC_OFF);   // staged C table
    float (*T)[SEQ]       = (float(*)[SEQ])(dsm + T_OFF);      // row-scan vals
    float (*s_acc)[SEQ]   = (float(*)[SEQ])(dsm + T_OFF);      // overlay (late)
    float (*segTot)[SEQ]  = (float(*)[SEQ])(dsm + SEG_OFF);
    float *offv           = (float*)(dsm + OFFV_OFF);
    float (*partbuf)[SEQ] = (float(*)[SEQ])(dsm + PART_OFF);

    const int b   = blockIdx.x >> 3;       // batch
    const int sub = blockIdx.x & 7;        // rank in cluster
    const int tid = threadIdx.x, w = tid >> 5, l = tid & 31;
    const int n0  = sub * 32;              // this block's 32 rows

    // zero the [SEQ],[SEQ+1] pads of every sC row (local)
    if (tid < 2*KMAX) sC[tid >> 1][SEQ + (tid & 1)] = 0.0f;

    // ---- phase 1: D + within-segment row-scan (thread = column) ----
    const float* cb = g_corr + (size_t)b * SEQ * SEQ;
    if (tid < SEQ) {
        const int i = tid;
        const float di = g_diag[b][i];
        float run = 0.0f;
        #pragma unroll
        for (int n = 0; n < 32; n++) {
            float dn = g_diag[b][n0 + n];
            float denom = sqrtf(fmaxf(dn * di, 1e-8f));
            float d = (1.0f - cb[(size_t)(n0 + n) * SEQ + i] / denom) * 0.5f;
            run += d;
            T[n][i] = run;
        }
        uint32_t a = smem_u32(&segTot[sub][i]);
        #pragma unroll
        for (int r = 0; r < CLUS; r++) dsmem_st(a, r, run);
    }
    cluster_sync_();                        // segTot complete everywhere

    if (tid < SEQ) {
        float o = 0.0f;
        #pragma unroll
        for (int sp = 0; sp < CLUS; sp++) if (sp < sub) o += segTot[sp][tid];
        offv[tid] = o;
    }
    __syncthreads();

    // ---- col-scan: warp w scans rows n0+2w, n0+2w+1; write P ----
    #pragma unroll
    for (int rr = 0; rr < 2; rr++) {
        int r = 2*w + rr;
        float v[8];
        #pragma unroll
        for (int j = 0; j < 8; j++) v[j] = T[r][l*8 + j] + offv[l*8 + j];
        #pragma unroll
        for (int j = 1; j < 8; j++) v[j] += v[j-1];
        float tot = v[7], inc = tot;
        #pragma unroll
        for (int d2 = 1; d2 < 32; d2 <<= 1) {
            float t2 = __shfl_up_sync(0xffffffffu, inc, d2);
            if (l >= d2) inc += t2;
        }
        float excl = inc - tot;
        float* P = g_P + ((size_t)b * SEQ + n0 + r) * SEQ;
        #pragma unroll
        for (int j = 0; j < 8; j++) __stcg(&P[l*8 + j], v[j] + excl);
    }
    __syncthreads();
    if (tid == 0) __threadfence();          // release P (cumulative)
    __syncthreads();
    cluster_sync_();
    if (tid == 0) __threadfence();          // acquire
    __syncthreads();

    // ---- build this warp's two Ds rows from P (registers) ----
    const int rb = n0 + 2*w;                // first owned row
    const float* Pb = g_P + (size_t)b * SEQ * SEQ;
    float rowv[2][8];
    float adiag[8];
    #pragma unroll
    for (int j = 0; j < 8; j++) adiag[j] = __ldcg(&Pb[(l + 32*j) * (SEQ + 1)]);
    #pragma unroll
    for (int rr = 0; rr < 2; rr++) {
        int wb = rb + rr;
        int nm1 = wb - 1;
        float dc = (wb == 0) ? 0.0f : __ldcg(&Pb[nm1*SEQ + nm1]);
        #pragma unroll
        for (int j = 0; j < 8; j++) {
            int i = l + 32*j;
            if (i >= wb) {
                float bb = (wb == 0) ? 0.0f : __ldcg(&Pb[nm1*SEQ + i]);
                float cc = (wb == 0) ? 0.0f : __ldcg(&Pb[i*SEQ + nm1]);
                rowv[rr][j] = ((adiag[j] - bb) - cc) + dc;
            } else {
                rowv[rr][j] = 3.0e38f;
            }
        }
        if (l == 31) {                      // publish C0[wb] = Ds[wb][255]
            uint32_t a = smem_u32(&sC[0][wb]);
            float v = rowv[rr][7];
            #pragma unroll
            for (int r = 0; r < CLUS; r++) dsmem_st(a, r, v);
        }
    }
    cluster_sync_();                        // C0 complete everywhere

    // ---- min-only DP: 29 steps, DSMEM broadcast + cluster barrier ----
    #pragma unroll 1
    for (int kk = 1; kk < KMAX; kk++) {
        const int limit = SEQ - kk;
        #pragma unroll
        for (int rr = 0; rr < 2; rr++) {
            const int wb = rb + rr;
            float val = 0.0f;
            if (wb < limit) {
                float mn = 3.0e38f;
                #pragma unroll
                for (int j = 0; j < 8; j++) {
                    int i = l + 32*j;
                    float t = (i < limit) ? (rowv[rr][j] + sC[kk-1][i + 1]) : 3.0e38f;
                    mn = fminf(mn, t);
                }
                #pragma unroll
                for (int o = 16; o > 0; o >>= 1)
                    mn = fminf(mn, __shfl_xor_sync(0xffffffffu, mn, o));
                val = mn;
            }
            if (l == 0) {
                uint32_t a = smem_u32(&sC[kk][wb]);
                #pragma unroll
                for (int r = 0; r < CLUS; r++) dsmem_st(a, r, val);
            }
        }
        cluster_sync_();
    }

    // ---- barrier-free softmax accumulation (all data in own smem) ----
    float acc[8] = {};
    #pragma unroll 1
    for (int rr = 0; rr < 2; rr++) {
        const int wb = rb + rr;
        #pragma unroll 1
        for (int kk = 1; kk < KMAX; kk++) {
            const int limit = SEQ - kk;
            if (wb >= limit) break;
            const float mn = sC[kk][wb];
            float e[8];
            float s = 0.0f;
            #pragma unroll
            for (int j = 0; j < 8; j++) {
                e[j] = 0.0f;
                if (32*j + 31 >= wb && 32*j < limit) {   // warp-uniform skip
                    int i = l + 32*j;
                    float t = (i < limit) ? (rowv[rr][j] + sC[kk-1][i + 1]) : 3.0e38f;
                    e[j] = __expf(mn - t);               // i<wb lanes -> 0
                    s += e[j];
                }
            }
            #pragma unroll
            for (int o = 16; o > 0; o >>= 1)
                s += __shfl_xor_sync(0xffffffffu, s, o);
            float inv = __fdividef(1.0f, s);
            #pragma unroll
            for (int j = 0; j < 8; j++) acc[j] += e[j] * inv;
        }
    }

    // ---- block reduce, cluster reduce to rank 0, final output ----
    __syncthreads();                        // T no longer needed (overlay s_acc)
    #pragma unroll
    for (int j = 0; j < 8; j++) s_acc[w][l + 32*j] = acc[j];
    __syncthreads();
    if (tid < SEQ) {
        float p = 0.0f;
        #pragma unroll
        for (int ww = 0; ww < 16; ww++) p += s_acc[ww][tid];
        dsmem_st(smem_u32(&partbuf[sub][tid]), 0, p);
    }
    cluster_sync_();
    if (sub == 0 && tid < SEQ) {
        const int i = tid;
        float num = (i == SEQ - 1) ? (float)SEQ : 0.0f;   // k=0 plane term
        #pragma unroll
        for (int r = 0; r < CLUS; r++) num += partbuf[r][i];
        int m = min(KMAX - 1, SEQ - 1 - i);
        float cnt = (float)((i + 1) * m + ((i == SEQ - 1) ? SEQ : 0));
        out[b*SEQ + i] = num / cnt;
    }
    cluster_sync_();                        // no early exit under peers' DSMEM
}

// ============================================================
extern "C" void kernel_launch(void* const* d_in, const int* in_sizes, int n_in,
                              void* d_out, int out_size)
{
    const float* x  = (const float*)d_in[0];
    const float* W0 = (const float*)d_in[1];
    const float* b0 = (const float*)d_in[2];
    const float* W1 = (const float*)d_in[3];
    const float* b1 = (const float*)d_in[4];
    float* out = (float*)d_out;

    static float* p_h = nullptr;
    static float* p_z = nullptr;
    if (!p_h) {
        cudaGetSymbolAddress((void**)&p_h, g_h);
        cudaGetSymbolAddress((void**)&p_z, g_z);
        cudaFuncSetAttribute(dp_kernel,
                             cudaFuncAttributeMaxDynamicSharedMemorySize, DSM_BYTES);
    }

    gemm_kernel<1><<<dim3(F1/64, (BATCH*SEQ)/64), 256>>>(x,   W0, b0, p_h, BATCH*SEQ, F1, F0);
    gemm_kernel<0><<<dim3(F2/64, (BATCH*SEQ)/64), 256>>>(p_h, W1, b1, p_z, BATCH*SEQ, F2, F1);
    syrk_kernel<<<dim3(SEQ/64, SEQ/64, BATCH), 256>>>();
    dp_kernel<<<BATCH*CLUS, DPT, DSM_BYTES>>>(out);
}